// round 16
// baseline (speedup 1.0000x reference)
#include <cuda_runtime.h>
#include <cuda_fp16.h>
#include <cstdint>

// Problem dims (fixed): inputs [4,2048,2048] f32, W1/W2 [2048,2048] f32.
#define MTOT 8192
#define NTOT 2048
#define KTOT 2048

// ---------------- scratch globals (no allocation allowed) ----------------
__device__ __align__(256) __half g_xn_h[(size_t)MTOT * NTOT];   // 32 MiB (xnorm, fp16)
__device__ __align__(256) __half g_h_h[(size_t)MTOT * NTOT];    // 32 MiB
__device__ __align__(256) __half g_w1t[(size_t)NTOT * KTOT];    // 8 MiB, transposed [n][k]
__device__ __align__(256) __half g_w2t[(size_t)NTOT * KTOT];    // 8 MiB
// sync counters: [0]=w1cnt(64) [1]=w2cnt(64) [2..66)=ln[m](4) [66..130)=cnt[m](16)
__device__ int g_sync[130];

// ---------------- helpers ----------------
__device__ __forceinline__ uint32_t smem_u32(const void* p) {
    uint32_t a;
    asm("{ .reg .u64 t; cvta.to.shared.u64 t, %1; cvt.u32.u64 %0, t; }" : "=r"(a) : "l"(p));
    return a;
}
__device__ __forceinline__ void cp16(uint32_t s, const void* g) {
    asm volatile("cp.async.cg.shared.global [%0], [%1], 16;" ::"r"(s), "l"(g));
}
__device__ __forceinline__ void mma16816(float* c, const uint32_t* a, uint32_t b0,
                                         uint32_t b1) {
    asm volatile(
        "mma.sync.aligned.m16n8k16.row.col.f32.f16.f16.f32 "
        "{%0,%1,%2,%3},{%4,%5,%6,%7},{%8,%9},{%0,%1,%2,%3};"
        : "+f"(c[0]), "+f"(c[1]), "+f"(c[2]), "+f"(c[3])
        : "r"(a[0]), "r"(a[1]), "r"(a[2]), "r"(a[3]), "r"(b0), "r"(b1));
}
__device__ __forceinline__ uint32_t pack_h2(float a, float b) {
    __half2 h = __floats2half2_rn(a, b);
    return *(uint32_t*)&h;
}

// ---------------- JAX threefry2x32 keep-decision (verified R6/R11) ----------------
#define TFR(r)                             \
    do {                                   \
        x0 += x1;                          \
        x1 = __funnelshift_l(x1, x1, (r)); \
        x1 ^= x0;                          \
    } while (0)
__device__ __forceinline__ bool tf_keep(uint32_t i) {
    uint32_t x0 = 0u, x1 = i;
    const uint32_t ks0 = 0u, ks1 = 1u, ks2 = 0x1BD11BDBu;
    x0 += ks0; x1 += ks1;
    TFR(13); TFR(15); TFR(26); TFR(6);
    x0 += ks1; x1 += ks2 + 1u;
    TFR(17); TFR(29); TFR(16); TFR(24);
    x0 += ks2; x1 += ks0 + 2u;
    TFR(13); TFR(15); TFR(26); TFR(6);
    x0 += ks0; x1 += ks1 + 3u;
    TFR(17); TFR(29); TFR(16); TFR(24);
    x0 += ks1; x1 += ks2 + 4u;
    TFR(13); TFR(15); TFR(26); TFR(6);
    x0 += ks2; x1 += ks0 + 5u;
    return (x0 ^ x1) < 0xC0000000u;  // uniform(bits) < 0.75 (verified bit-identical)
}

// ---------------- transpose one 32x32 tile of W (fp32) into Wt (fp16, [n][k]) --------
__device__ __forceinline__ void w_transpose_tile(const float* __restrict__ W,
                                                 __half* __restrict__ Wt, int bb,
                                                 float (*tile)[33], int t) {
    const int bx = (bb & 63) * 32;  // n block
    const int by = (bb >> 6) * 32;  // k block
    const int tx = t & 31;
    const int ty = t >> 5;  // 0..7
#pragma unroll
    for (int j = 0; j < 32; j += 8)
        tile[ty + j][tx] = W[(size_t)(by + ty + j) * NTOT + bx + tx];
    __syncthreads();
#pragma unroll
    for (int j = 0; j < 32; j += 8) {
        const int n = bx + ty + j, k = by + tx;
        Wt[(size_t)n * KTOT + k] = __float2half_rn(tile[tx][ty + j]);
    }
}

// ---------------- single fused kernel: prep | phase-0 GEMM | phase-1 GEMM ------------
// Grid (16, 152), bid = x + 16*y (y-major ordering):
//   y in [0,24):    prep, pid = bid in [0,384):
//       pid <  64 : W1 transpose, 64 tiles each        -> g_sync[0] (target 64)
//       pid < 128 : W2 transpose, 64 tiles each        -> g_sync[1] (target 64)
//       pid < 384 : LayerNorm, 32 rows each            -> g_sync[2+m] (target 4)
//   y in [24,88):   phase-0 tile (h = relu(xn @ W1));  -> g_sync[66+m] (target 16)
//   y in [88,152):  phase-1 tile (out = xn + dropout(h @ W2))
// Waiters' producers strictly precede them in bid order and never wait -> no deadlock
// (same argument as R14, which passed). Counters zeroed by cudaMemsetAsync pre-launch.
// GEMM inner loop: R9-proven shape — CTA 128x128, 8 warps 64x32, K-chunk 32,
// 4-stage cp.async, 2 CTAs/SM.
#define APITCH 80
#define SM_B_OFF 10240
#define STAGE_BYTES 20480
#define GEMM_SMEM (4 * STAGE_BYTES)

__global__ void __launch_bounds__(256, 2) fused_all(float* __restrict__ Cext,
                                                    const float* __restrict__ in,
                                                    const float* __restrict__ W1,
                                                    const float* __restrict__ W2) {
    extern __shared__ __align__(128) char smem[];
    const uint32_t sb = smem_u32(smem);
    const int tid = threadIdx.x;

    if (blockIdx.y < 24) {
        const int pid = (int)blockIdx.x + 16 * (int)blockIdx.y;  // 0..383
        if (pid < 128) {
            // ---- W transpose: 64 tiles per CTA ----
            const float* W = (pid < 64) ? W1 : W2;
            __half* Wt = (pid < 64) ? g_w1t : g_w2t;
            const int base = (pid & 63) * 64;
            float(*tile)[33] = (float(*)[33])smem;
#pragma unroll 1
            for (int j = 0; j < 64; j++) {
                w_transpose_tile(W, Wt, base + j, tile, tid);
                __syncthreads();
            }
            __threadfence();
            __syncthreads();
            if (tid == 0) atomicAdd(&g_sync[(pid < 64) ? 0 : 1], 1);
        } else {
            // ---- LayerNorm: 32 rows per CTA (fp16 out; residual read back fp16) ----
            const int r0 = (pid - 128) * 32;
            __shared__ float rs[8], rq[8];
#pragma unroll 1
            for (int r = 0; r < 32; r++) {
                const int row = r0 + r;
                const float4* ip = (const float4*)(in + (size_t)row * NTOT);
                float4 v0 = ip[tid];
                float4 v1 = ip[tid + 256];
                float s = v0.x + v0.y + v0.z + v0.w + v1.x + v1.y + v1.z + v1.w;
                float q = v0.x * v0.x + v0.y * v0.y + v0.z * v0.z + v0.w * v0.w +
                          v1.x * v1.x + v1.y * v1.y + v1.z * v1.z + v1.w * v1.w;
#pragma unroll
                for (int o = 16; o > 0; o >>= 1) {
                    s += __shfl_xor_sync(0xffffffffu, s, o);
                    q += __shfl_xor_sync(0xffffffffu, q, o);
                }
                if ((tid & 31) == 0) { rs[tid >> 5] = s; rq[tid >> 5] = q; }
                __syncthreads();
                if (tid < 8) {
                    s = rs[tid]; q = rq[tid];
#pragma unroll
                    for (int o = 4; o > 0; o >>= 1) {
                        s += __shfl_xor_sync(0xffu, s, o);
                        q += __shfl_xor_sync(0xffu, q, o);
                    }
                    if (tid == 0) { rs[0] = s; rq[0] = q; }
                }
                __syncthreads();
                const float mean = rs[0] * (1.0f / (float)NTOT);
                const float var = rq[0] * (1.0f / (float)NTOT) - mean * mean;
                const float rstd = rsqrtf(var + 1e-6f);
                uint2* hp = (uint2*)(g_xn_h + (size_t)row * NTOT);
                uint2 h0, h1;
                h0.x = pack_h2((v0.x - mean) * rstd, (v0.y - mean) * rstd);
                h0.y = pack_h2((v0.z - mean) * rstd, (v0.w - mean) * rstd);
                h1.x = pack_h2((v1.x - mean) * rstd, (v1.y - mean) * rstd);
                h1.y = pack_h2((v1.z - mean) * rstd, (v1.w - mean) * rstd);
                hp[tid] = h0;
                hp[tid + 256] = h1;
                __syncthreads();  // protect rs/rq reuse next row
            }
            __threadfence();
            __syncthreads();
            if (tid == 0) atomicAdd(&g_sync[2 + (r0 >> 7)], 1);
        }
        return;
    }

    const int phase = (blockIdx.y >= 88);
    const int mblk = (int)blockIdx.y - (phase ? 88 : 24);
    const int m0 = mblk * 128;
    const int n0 = blockIdx.x * 128;

    const __half* __restrict__ Ag = phase ? g_h_h : g_xn_h;
    const __half* __restrict__ Bg = phase ? g_w2t : g_w1t;

    // Wait for producers (phase-0: W1 + LN of this m-block; phase-1: W2 + 16 tiles).
    if (tid == 0) {
        volatile int* w = &g_sync[phase ? 1 : 0];
        volatile int* f = phase ? &g_sync[66 + mblk] : &g_sync[2 + mblk];
        const int ft = phase ? 16 : 4;
        while (*w < 64 || *f < ft) __nanosleep(200);
    }
    __syncthreads();
    __threadfence();  // acquire: order A/B loads after observed counts

    // Loader: A/B each 128 rows x 4 16B-vecs per chunk; thread -> row tid/2, 2 vecs.
    const int lrow = tid >> 1;
    const int lv = (tid & 1) * 2;  // vec index 0 or 2
    const __half* agp = Ag + (size_t)(m0 + lrow) * KTOT + lv * 8;
    const __half* bgp = Bg + (size_t)(n0 + lrow) * KTOT + lv * 8;
    const uint32_t a_soff = (uint32_t)(lrow * APITCH + lv * 16);
    const uint32_t b_soff = (uint32_t)(SM_B_OFF + lrow * APITCH + lv * 16);

#define LOAD_STAGE(sidx, kc)                            \
    do {                                                \
        const uint32_t _st = sb + (sidx) * STAGE_BYTES; \
        cp16(_st + a_soff, agp + (kc));                 \
        cp16(_st + a_soff + 16, agp + (kc) + 8);        \
        cp16(_st + b_soff, bgp + (kc));                 \
        cp16(_st + b_soff + 16, bgp + (kc) + 8);        \
    } while (0)

    LOAD_STAGE(0, 0);
    asm volatile("cp.async.commit_group;" ::: "memory");
    LOAD_STAGE(1, 32);
    asm volatile("cp.async.commit_group;" ::: "memory");
    LOAD_STAGE(2, 64);
    asm volatile("cp.async.commit_group;" ::: "memory");

    const int lane = tid & 31;
    const int wid = tid >> 5;
    const int wm = (wid >> 2) * 64;  // 0,64
    const int wn = (wid & 3) * 32;   // 0..96

    float acc[4][4][4];
#pragma unroll
    for (int mt = 0; mt < 4; mt++)
#pragma unroll
        for (int nt = 0; nt < 4; nt++)
#pragma unroll
            for (int j = 0; j < 4; j++) acc[mt][nt][j] = 0.0f;

    // ldmatrix bases (byte offsets within a stage).
    const uint32_t a_lm = (uint32_t)((wm + (lane & 15)) * APITCH + (lane >> 4) * 16);
    const uint32_t b_lm = (uint32_t)(SM_B_OFF +
                                     (wn + (lane & 7) + ((lane >> 4) << 3)) * APITCH +
                                     ((lane >> 3) & 1) * 16);

#pragma unroll 1
    for (int c = 0; c < KTOT / 32; c++) {
        asm volatile("cp.async.wait_group 2;" ::: "memory");
        __syncthreads();
        if (c + 3 < KTOT / 32) LOAD_STAGE((c + 3) & 3, (c + 3) * 32);
        asm volatile("cp.async.commit_group;" ::: "memory");

        const uint32_t st = sb + (c & 3) * STAGE_BYTES;
#pragma unroll
        for (int h = 0; h < 2; h++) {
            const uint32_t kb = h * 32;
            uint32_t a[4][4];
#pragma unroll
            for (int mt = 0; mt < 4; mt++) {
                const uint32_t addr = st + a_lm + mt * 16 * APITCH + kb;
                asm volatile(
                    "ldmatrix.sync.aligned.m8n8.x4.shared.b16 {%0,%1,%2,%3},[%4];"
                    : "=r"(a[mt][0]), "=r"(a[mt][1]), "=r"(a[mt][2]), "=r"(a[mt][3])
                    : "r"(addr));
            }
            uint32_t b[2][4];  // [pair][{nt0.b0, nt0.b1, nt1.b0, nt1.b1}]
#pragma unroll
            for (int p = 0; p < 2; p++) {
                const uint32_t addr = st + b_lm + p * 16 * APITCH + kb;
                asm volatile(
                    "ldmatrix.sync.aligned.m8n8.x4.shared.b16 {%0,%1,%2,%3},[%4];"
                    : "=r"(b[p][0]), "=r"(b[p][1]), "=r"(b[p][2]), "=r"(b[p][3])
                    : "r"(addr));
            }
#pragma unroll
            for (int nt = 0; nt < 4; nt++) {
                const uint32_t b0 = b[nt >> 1][(nt & 1) * 2];
                const uint32_t b1 = b[nt >> 1][(nt & 1) * 2 + 1];
#pragma unroll
                for (int mt = 0; mt < 4; mt++) mma16816(acc[mt][nt], a[mt], b0, b1);
            }
        }
    }

    // ---------------- epilogue ----------------
    const int rbase = m0 + wm + (lane >> 2);
    const int cbase = n0 + wn + (lane & 3) * 2;
    const float sc = 1.0f / 0.75f;
#pragma unroll
    for (int mt = 0; mt < 4; mt++) {
#pragma unroll
        for (int half = 0; half < 2; half++) {
            const int row = rbase + mt * 16 + half * 8;
            const size_t rowb = (size_t)row * NTOT;
#pragma unroll
            for (int nt = 0; nt < 4; nt++) {
                const int col = cbase + nt * 8;
                const float v0 = acc[mt][nt][2 * half];
                const float v1 = acc[mt][nt][2 * half + 1];
                if (!phase) {
                    *(uint32_t*)(g_h_h + rowb + col) =
                        pack_h2(fmaxf(v0, 0.0f), fmaxf(v1, 0.0f));
                } else {
                    const uint32_t i0 = (uint32_t)(rowb + col);
                    const uint32_t xb = *(const uint32_t*)(g_xn_h + rowb + col);
                    const float2 xr = __half22float2(*(const __half2*)&xb);
                    float2 o;
                    o.x = xr.x + (tf_keep(i0) ? v0 * sc : 0.0f);
                    o.y = xr.y + (tf_keep(i0 + 1u) ? v1 * sc : 0.0f);
                    *(float2*)(Cext + rowb + col) = o;
                }
            }
        }
    }

    // Phase-0: publish this tile (release: fence then count).
    if (!phase) {
        __threadfence();
        __syncthreads();
        if (tid == 0) atomicAdd(&g_sync[66 + mblk], 1);
    }
#undef LOAD_STAGE
}

extern "C" void kernel_launch(void* const* d_in, const int* in_sizes, int n_in,
                              void* d_out, int out_size) {
    const float* inputs = (const float*)d_in[0];
    const float* W1 = (const float*)d_in[1];
    const float* W2 = (const float*)d_in[2];
    float* out = (float*)d_out;
    (void)in_sizes; (void)n_in; (void)out_size;

    cudaFuncSetAttribute(fused_all, cudaFuncAttributeMaxDynamicSharedMemorySize,
                         GEMM_SMEM);

    void* sync_addr = nullptr;
    cudaGetSymbolAddress(&sync_addr, g_sync);
    cudaMemsetAsync(sync_addr, 0, sizeof(int) * 130, 0);

    dim3 grid(16, 152);
    fused_all<<<grid, 256, GEMM_SMEM>>>(out, inputs, W1, W2);
}

// round 17
// speedup vs baseline: 1.1046x; 1.1046x over previous
#include <cuda_runtime.h>
#include <cuda_fp16.h>
#include <cstdint>

// Problem dims (fixed): inputs [4,2048,2048] f32, W1/W2 [2048,2048] f32.
#define MTOT 8192
#define NTOT 2048
#define KTOT 2048

// ---------------- scratch globals (no allocation allowed) ----------------
__device__ __align__(256) __half g_xn_h[(size_t)MTOT * NTOT];   // 32 MiB (xnorm, fp16)
__device__ __align__(256) __half g_h_h[(size_t)MTOT * NTOT];    // 32 MiB
__device__ __align__(256) __half g_w1t[(size_t)NTOT * KTOT];    // 8 MiB, transposed [n][k]
__device__ __align__(256) __half g_w2t[(size_t)NTOT * KTOT];    // 8 MiB
__device__ int g_cnt[MTOT / 128];  // per-M-block phase-0 completion counters

// ---------------- helpers ----------------
__device__ __forceinline__ uint32_t smem_u32(const void* p) {
    uint32_t a;
    asm("{ .reg .u64 t; cvta.to.shared.u64 t, %1; cvt.u32.u64 %0, t; }" : "=r"(a) : "l"(p));
    return a;
}
__device__ __forceinline__ void cp16(uint32_t s, const void* g) {
    asm volatile("cp.async.cg.shared.global [%0], [%1], 16;" ::"r"(s), "l"(g));
}
__device__ __forceinline__ void mma16816(float* c, const uint32_t* a, uint32_t b0,
                                         uint32_t b1) {
    asm volatile(
        "mma.sync.aligned.m16n8k16.row.col.f32.f16.f16.f32 "
        "{%0,%1,%2,%3},{%4,%5,%6,%7},{%8,%9},{%0,%1,%2,%3};"
        : "+f"(c[0]), "+f"(c[1]), "+f"(c[2]), "+f"(c[3])
        : "r"(a[0]), "r"(a[1]), "r"(a[2]), "r"(a[3]), "r"(b0), "r"(b1));
}
__device__ __forceinline__ uint32_t pack_h2(float a, float b) {
    __half2 h = __floats2half2_rn(a, b);
    return *(uint32_t*)&h;
}

// ---------------- JAX threefry2x32 keep-decision (verified R6/R11) ----------------
#define TFR(r)                             \
    do {                                   \
        x0 += x1;                          \
        x1 = __funnelshift_l(x1, x1, (r)); \
        x1 ^= x0;                          \
    } while (0)
__device__ __forceinline__ bool tf_keep(uint32_t i) {
    uint32_t x0 = 0u, x1 = i;
    const uint32_t ks0 = 0u, ks1 = 1u, ks2 = 0x1BD11BDBu;
    x0 += ks0; x1 += ks1;
    TFR(13); TFR(15); TFR(26); TFR(6);
    x0 += ks1; x1 += ks2 + 1u;
    TFR(17); TFR(29); TFR(16); TFR(24);
    x0 += ks2; x1 += ks0 + 2u;
    TFR(13); TFR(15); TFR(26); TFR(6);
    x0 += ks0; x1 += ks1 + 3u;
    TFR(17); TFR(29); TFR(16); TFR(24);
    x0 += ks1; x1 += ks2 + 4u;
    TFR(13); TFR(15); TFR(26); TFR(6);
    x0 += ks2; x1 += ks0 + 5u;
    return (x0 ^ x1) < 0xC0000000u;  // uniform(bits) < 0.75 (verified bit-identical)
}

// ---------------- fused prep: W1 transpose | W2 transpose | LayerNorm ----------------
// blocks [0,4096): W1 32x32 transpose tiles; [4096,8192): W2; [8192,16384): LN rows.
// Block 0 also zeroes the phase counters for this launch (graph-replay safe).
__global__ void __launch_bounds__(256) prep_all(const float* __restrict__ in,
                                                const float* __restrict__ W1,
                                                const float* __restrict__ W2) {
    const int b = blockIdx.x;
    const int t = threadIdx.x;
    if (b < 8192) {
        if (b == 0 && t < MTOT / 128) g_cnt[t] = 0;
        // ---- weight transpose + fp16 ----
        const float* W = (b < 4096) ? W1 : W2;
        __half* Wt = (b < 4096) ? g_w1t : g_w2t;
        const int bb = b & 4095;
        __shared__ float tile[32][33];
        const int bx = (bb & 63) * 32;  // n block
        const int by = (bb >> 6) * 32;  // k block
        const int tx = t & 31;
        const int ty = t >> 5;  // 0..7
#pragma unroll
        for (int j = 0; j < 32; j += 8)
            tile[ty + j][tx] = W[(size_t)(by + ty + j) * NTOT + bx + tx];
        __syncthreads();
#pragma unroll
        for (int j = 0; j < 32; j += 8) {
            const int n = bx + ty + j, k = by + tx;
            Wt[(size_t)n * KTOT + k] = __float2half_rn(tile[tx][ty + j]);
        }
        return;
    }
    // ---- LayerNorm row (fp16 output only; residual read back as fp16) ----
    const int row = b - 8192;
    const float4* ip = (const float4*)(in + (size_t)row * NTOT);

    float4 v0 = ip[t];
    float4 v1 = ip[t + 256];
    float s = v0.x + v0.y + v0.z + v0.w + v1.x + v1.y + v1.z + v1.w;
    float q = v0.x * v0.x + v0.y * v0.y + v0.z * v0.z + v0.w * v0.w +
              v1.x * v1.x + v1.y * v1.y + v1.z * v1.z + v1.w * v1.w;

#pragma unroll
    for (int o = 16; o > 0; o >>= 1) {
        s += __shfl_xor_sync(0xffffffffu, s, o);
        q += __shfl_xor_sync(0xffffffffu, q, o);
    }
    __shared__ float rs[8], rq[8];
    if ((t & 31) == 0) { rs[t >> 5] = s; rq[t >> 5] = q; }
    __syncthreads();
    if (t < 8) {
        s = rs[t]; q = rq[t];
#pragma unroll
        for (int o = 4; o > 0; o >>= 1) {
            s += __shfl_xor_sync(0xffu, s, o);
            q += __shfl_xor_sync(0xffu, q, o);
        }
        if (t == 0) { rs[0] = s; rq[0] = q; }
    }
    __syncthreads();

    const float mean = rs[0] * (1.0f / (float)NTOT);
    const float var = rq[0] * (1.0f / (float)NTOT) - mean * mean;
    const float rstd = rsqrtf(var + 1e-6f);

    uint2* hp = (uint2*)(g_xn_h + (size_t)row * NTOT);
    uint2 h0, h1;
    h0.x = pack_h2((v0.x - mean) * rstd, (v0.y - mean) * rstd);
    h0.y = pack_h2((v0.z - mean) * rstd, (v0.w - mean) * rstd);
    h1.x = pack_h2((v1.x - mean) * rstd, (v1.y - mean) * rstd);
    h1.y = pack_h2((v1.z - mean) * rstd, (v1.w - mean) * rstd);
    hp[t] = h0;
    hp[t + 256] = h1;
}

// ---------------- fused dual-phase HMMA GEMM (R14 winner + 5-stage pipeline) --------
// One launch, grid (16, 128). blockIdx.y < 64: phase 0 tile (h = relu(xn@W1)),
// else phase 1 tile (out = xn + dropout(h@W2)). Phase 1 CTA (m,n) spin-waits on
// g_cnt[m] == 16 before its first h load. Inner loop: R9-proven shape —
// CTA 128x128, 8 warps 64x32, K-chunk 32, now 5-stage cp.async, 2 CTAs/SM.
#define APITCH 80
#define SM_B_OFF 10240
#define STAGE_BYTES 20480
#define NSTAGE 5
#define GEMM_SMEM (NSTAGE * STAGE_BYTES)

__global__ void __launch_bounds__(256, 2) gemm_fused(float* __restrict__ Cext) {
    extern __shared__ __align__(128) char smem[];
    const uint32_t sb = smem_u32(smem);
    const int tid = threadIdx.x;

    const int phase = (blockIdx.y >= 64);
    const int mblk = blockIdx.y & 63;
    const int m0 = mblk * 128;
    const int n0 = blockIdx.x * 128;

    const __half* __restrict__ Ag = phase ? g_h_h : g_xn_h;
    const __half* __restrict__ Bg = phase ? g_w2t : g_w1t;

    // Phase-1: wait for all 16 producer tiles of this M row-block.
    if (phase) {
        if (tid == 0) {
            volatile int* f = &g_cnt[mblk];
            while (*f < 16) __nanosleep(200);
        }
        __syncthreads();
        __threadfence();  // acquire: order h loads after observed count
    }

    // Loader: A/B each 128 rows x 4 16B-vecs per chunk; thread -> row tid/2, 2 vecs.
    const int lrow = tid >> 1;
    const int lv = (tid & 1) * 2;  // vec index 0 or 2
    const __half* agp = Ag + (size_t)(m0 + lrow) * KTOT + lv * 8;
    const __half* bgp = Bg + (size_t)(n0 + lrow) * KTOT + lv * 8;
    const uint32_t a_soff = (uint32_t)(lrow * APITCH + lv * 16);
    const uint32_t b_soff = (uint32_t)(SM_B_OFF + lrow * APITCH + lv * 16);

#define LOAD_STAGE(sidx, kc)                            \
    do {                                                \
        const uint32_t _st = sb + (sidx) * STAGE_BYTES; \
        cp16(_st + a_soff, agp + (kc));                 \
        cp16(_st + a_soff + 16, agp + (kc) + 8);        \
        cp16(_st + b_soff, bgp + (kc));                 \
        cp16(_st + b_soff + 16, bgp + (kc) + 8);        \
    } while (0)

    LOAD_STAGE(0, 0);
    asm volatile("cp.async.commit_group;" ::: "memory");
    LOAD_STAGE(1, 32);
    asm volatile("cp.async.commit_group;" ::: "memory");
    LOAD_STAGE(2, 64);
    asm volatile("cp.async.commit_group;" ::: "memory");
    LOAD_STAGE(3, 96);
    asm volatile("cp.async.commit_group;" ::: "memory");

    const int lane = tid & 31;
    const int wid = tid >> 5;
    const int wm = (wid >> 2) * 64;  // 0,64
    const int wn = (wid & 3) * 32;   // 0..96

    float acc[4][4][4];
#pragma unroll
    for (int mt = 0; mt < 4; mt++)
#pragma unroll
        for (int nt = 0; nt < 4; nt++)
#pragma unroll
            for (int j = 0; j < 4; j++) acc[mt][nt][j] = 0.0f;

    // ldmatrix bases (byte offsets within a stage).
    const uint32_t a_lm = (uint32_t)((wm + (lane & 15)) * APITCH + (lane >> 4) * 16);
    const uint32_t b_lm = (uint32_t)(SM_B_OFF +
                                     (wn + (lane & 7) + ((lane >> 4) << 3)) * APITCH +
                                     ((lane >> 3) & 1) * 16);

    int sidx = 0;  // stage index of chunk c (avoids % NSTAGE)
#pragma unroll 1
    for (int c = 0; c < KTOT / 32; c++) {
        asm volatile("cp.async.wait_group 3;" ::: "memory");
        __syncthreads();
        if (c + 4 < KTOT / 32) {
            int ps = sidx + 4;
            if (ps >= NSTAGE) ps -= NSTAGE;
            LOAD_STAGE(ps, (c + 4) * 32);
        }
        asm volatile("cp.async.commit_group;" ::: "memory");

        const uint32_t st = sb + sidx * STAGE_BYTES;
        if (++sidx == NSTAGE) sidx = 0;
#pragma unroll
        for (int h = 0; h < 2; h++) {
            const uint32_t kb = h * 32;
            uint32_t a[4][4];
#pragma unroll
            for (int mt = 0; mt < 4; mt++) {
                const uint32_t addr = st + a_lm + mt * 16 * APITCH + kb;
                asm volatile(
                    "ldmatrix.sync.aligned.m8n8.x4.shared.b16 {%0,%1,%2,%3},[%4];"
                    : "=r"(a[mt][0]), "=r"(a[mt][1]), "=r"(a[mt][2]), "=r"(a[mt][3])
                    : "r"(addr));
            }
            uint32_t b[2][4];  // [pair][{nt0.b0, nt0.b1, nt1.b0, nt1.b1}]
#pragma unroll
            for (int p = 0; p < 2; p++) {
                const uint32_t addr = st + b_lm + p * 16 * APITCH + kb;
                asm volatile(
                    "ldmatrix.sync.aligned.m8n8.x4.shared.b16 {%0,%1,%2,%3},[%4];"
                    : "=r"(b[p][0]), "=r"(b[p][1]), "=r"(b[p][2]), "=r"(b[p][3])
                    : "r"(addr));
            }
#pragma unroll
            for (int nt = 0; nt < 4; nt++) {
                const uint32_t b0 = b[nt >> 1][(nt & 1) * 2];
                const uint32_t b1 = b[nt >> 1][(nt & 1) * 2 + 1];
#pragma unroll
                for (int mt = 0; mt < 4; mt++) mma16816(acc[mt][nt], a[mt], b0, b1);
            }
        }
    }

    // ---------------- epilogue ----------------
    const int rbase = m0 + wm + (lane >> 2);
    const int cbase = n0 + wn + (lane & 3) * 2;
    const float sc = 1.0f / 0.75f;
#pragma unroll
    for (int mt = 0; mt < 4; mt++) {
#pragma unroll
        for (int half = 0; half < 2; half++) {
            const int row = rbase + mt * 16 + half * 8;
            const size_t rowb = (size_t)row * NTOT;
#pragma unroll
            for (int nt = 0; nt < 4; nt++) {
                const int col = cbase + nt * 8;
                const float v0 = acc[mt][nt][2 * half];
                const float v1 = acc[mt][nt][2 * half + 1];
                if (!phase) {
                    *(uint32_t*)(g_h_h + rowb + col) =
                        pack_h2(fmaxf(v0, 0.0f), fmaxf(v1, 0.0f));
                } else {
                    const uint32_t i0 = (uint32_t)(rowb + col);
                    const uint32_t xb = *(const uint32_t*)(g_xn_h + rowb + col);
                    const float2 xr = __half22float2(*(const __half2*)&xb);
                    float2 o;
                    o.x = xr.x + (tf_keep(i0) ? v0 * sc : 0.0f);
                    o.y = xr.y + (tf_keep(i0 + 1u) ? v1 * sc : 0.0f);
                    *(float2*)(Cext + rowb + col) = o;
                }
            }
        }
    }

    // Phase-0: publish this tile (release: fence then count).
    if (!phase) {
        __threadfence();
        __syncthreads();
        if (tid == 0) atomicAdd(&g_cnt[mblk], 1);
    }
#undef LOAD_STAGE
}

extern "C" void kernel_launch(void* const* d_in, const int* in_sizes, int n_in,
                              void* d_out, int out_size) {
    const float* inputs = (const float*)d_in[0];
    const float* W1 = (const float*)d_in[1];
    const float* W2 = (const float*)d_in[2];
    float* out = (float*)d_out;
    (void)in_sizes; (void)n_in; (void)out_size;

    cudaFuncSetAttribute(gemm_fused, cudaFuncAttributeMaxDynamicSharedMemorySize, GEMM_SMEM);

    prep_all<<<16384, 256>>>(inputs, W1, W2);

    dim3 grid(NTOT / 128, 2 * (MTOT / 128));
    gemm_fused<<<grid, 256, GEMM_SMEM>>>(out);
}